// round 16
// baseline (speedup 1.0000x reference)
#include <cuda_runtime.h>

// Piecewise-linear log-sigmoid approximation (table interp).
// inputs: vals[64*2048*2048] f32, x[65] f32 (uniform linspace), y[65] f32
// output: f32 same shape.
//
// Semantics (matches jax reference):
//   v <  x[0]  -> v
//   v >= x[64] -> 0
//   else out = y[i] + (v - x[i]) * slope[i],  i = floor((v-x0)/h) clamped
//
// 4096 blocks x 256 threads, grid-stride with exact trip count, ILP=4
// float4/thread/iter, software-pipelined double buffer (prefetch next
// iteration's loads before this iteration's stores). The final iteration
// is PEELED so no redundant prefetch traffic is issued.

#define NBP  65
#define NSEG 64
#define ILP  4
#define THREADS 256
#define BLOCKS  4096
// per grid-iter float4s: 4096*256*4 = 2^22 ; n4 = 2^26 -> exactly 16 iters.

__device__ __forceinline__ void compute_store(
        float4* __restrict__ out4, unsigned int base,
        const float4 (&cur)[ILP],
        const float2* __restrict__ coef,
        float x0, float xlast, float invh)
{
    #pragma unroll
    for (int j = 0; j < ILP; j++) {
        float vv[4] = {cur[j].x, cur[j].y, cur[j].z, cur[j].w};
        float oo[4];
        #pragma unroll
        for (int k = 0; k < 4; k++) {
            float val = vv[k];
            int idx = (int)((val - x0) * invh);
            idx = max(0, min(idx, NSEG - 1));
            float2 c = coef[idx];
            float r = fmaf(c.y, val, c.x);
            r = (val <  x0)    ? val  : r;
            r = (val >= xlast) ? 0.0f : r;
            oo[k] = r;
        }
        float4 o;
        o.x = oo[0]; o.y = oo[1]; o.z = oo[2]; o.w = oo[3];
        __stcs(&out4[base + j * THREADS], o);
    }
}

__global__ __launch_bounds__(THREADS) void logsig_kernel(
        const float* __restrict__ vals,
        const float* __restrict__ xs,
        const float* __restrict__ ys,
        float* __restrict__ out,
        unsigned int niter)
{
    // Per-segment affine coefficients: r = c.x + c.y * v
    __shared__ float2 coef[NSEG];
    __shared__ float s_x0, s_xlast, s_invh;

    const unsigned int t = threadIdx.x;
    if (t < NSEG) {
        float x0 = xs[t];
        float x1 = xs[t + 1];
        float y0 = ys[t];
        float y1 = ys[t + 1];
        float slope = (y1 - y0) / (x1 - x0);
        coef[t] = make_float2(fmaf(-x0, slope, y0), slope);
    }
    if (t == 0) {
        float a = xs[0];
        float b = xs[NBP - 1];
        s_x0    = a;
        s_xlast = b;
        s_invh  = (float)NSEG / (b - a);
    }
    __syncthreads();

    const float x0    = s_x0;
    const float xlast = s_xlast;
    const float invh  = s_invh;

    const float4* __restrict__ in4  = reinterpret_cast<const float4*>(vals);
    float4* __restrict__       out4 = reinterpret_cast<float4*>(out);

    const unsigned int stride = (unsigned int)gridDim.x * (THREADS * ILP);
    unsigned int base = blockIdx.x * (THREADS * ILP) + t;

    // Prologue: load iteration 0
    float4 cur[ILP];
    #pragma unroll
    for (int j = 0; j < ILP; j++)
        cur[j] = __ldcs(&in4[base + j * THREADS]);

    // Steady state: prefetch next, then compute+store current. niter-1 times.
    for (unsigned int it = 0; it + 1 < niter; it++) {
        unsigned int nbase = base + stride;

        float4 nxt[ILP];
        #pragma unroll
        for (int j = 0; j < ILP; j++)
            nxt[j] = __ldcs(&in4[nbase + j * THREADS]);

        compute_store(out4, base, cur, coef, x0, xlast, invh);

        #pragma unroll
        for (int j = 0; j < ILP; j++)
            cur[j] = nxt[j];
        base = nbase;
    }

    // Epilogue: last iteration, no prefetch.
    compute_store(out4, base, cur, coef, x0, xlast, invh);
}

extern "C" void kernel_launch(void* const* d_in, const int* in_sizes, int n_in,
                              void* d_out, int out_size)
{
    const float* vals = (const float*)d_in[0];
    const float* xs   = (const float*)d_in[1];
    const float* ys   = (const float*)d_in[2];
    float* out        = (float*)d_out;

    unsigned int n4 = (unsigned int)(out_size / 4);      // 2^26 float4s
    unsigned int per_iter = BLOCKS * THREADS * ILP;      // 2^22 float4s
    unsigned int niter = (n4 + per_iter - 1) / per_iter; // 16 for this shape

    logsig_kernel<<<BLOCKS, THREADS>>>(vals, xs, ys, out, niter);
}